// round 15
// baseline (speedup 1.0000x reference)
#include <cuda_runtime.h>
#include <math.h>
#include <stdint.h>

typedef unsigned long long ull;

// Problem constants
constexpr int S_   = 128;   // sequence length
constexpr int B_   = 64;    // batch
constexpr int E_   = 256;   // embedding dim
constexpr int H_   = 256;   // hidden
constexpr int G4_  = 1024;  // 4*H (gates)
constexpr int HID_ = 30;    // attention hidden
constexpr int NCTA_DIR = 64;   // CTAs per direction in persistent step kernel

// Scratch (static device globals — no runtime allocation)
__device__ float g_emb[S_ * B_ * E_];        // (t,b,e)
__device__ float g_embT[E_ * S_ * B_];       // transposed: [e][t*B+b]
__device__ float g_WihT2[2 * E_ * 2 * G4_];  // transposed Wih, DUPLICATED: [e][2n]={w,w}
__device__ float g_X[2 * S_ * B_ * G4_];     // x-projections per dir, bias folded in
__device__ float g_h[2 * S_ * B_ * H_];      // [dir][t][b][k]  (for K4)
__device__ float g_hT[2][2][H_][B_];         // ping-pong [dir][parity][k][b]
__device__ int   g_bar[2 * S_];              // grid-barrier arrival counters
__device__ float g_U[B_ * S_ * HID_];        // u = enc @ Ua^T
__device__ float g_Wt[B_ * HID_ * S_];       // w transposed: [b][k][s]

// fast activations: MUFU-based, rel err ~2e-7 (budget is 1e-3)
__device__ __forceinline__ float fsig(float x)  { return 1.0f / (1.0f + __expf(-x)); }
__device__ __forceinline__ float ftanh(float x) { return 2.0f / (1.0f + __expf(-2.0f * x)) - 1.0f; }

// pure (non-volatile) packed fp32 math — scheduler may move these freely
__device__ __forceinline__ void ffma2(ull& d, ull a, ull b) {
    asm("fma.rn.f32x2 %0, %1, %2, %0;" : "+l"(d) : "l"(a), "l"(b));
}
__device__ __forceinline__ ull pack2(float lo, float hi) {
    ull r; asm("mov.b64 %0, {%1, %2};" : "=l"(r) : "f"(lo), "f"(hi)); return r;
}
__device__ __forceinline__ float2 unpack2(ull v) {
    float2 r; asm("mov.b64 {%0, %1}, %2;" : "=f"(r.x), "=f"(r.y) : "l"(v)); return r;
}
// L1-bypassing 16B load (h produced by other CTAs within this launch)
__device__ __forceinline__ void ldcg128(ull& x, ull& y, const float* p) {
    asm volatile("ld.global.cg.v2.u64 {%0, %1}, [%2];" : "=l"(x), "=l"(y) : "l"(p));
}
__device__ __forceinline__ void stcg32(float* p, float v) {
    asm volatile("st.global.cg.f32 [%0], %1;" :: "l"(p), "f"(v));
}
__device__ __forceinline__ void cp16(uint32_t smem_dst, const void* gsrc) {
    asm volatile("cp.async.cg.shared.global [%0], [%1], 16;" :: "r"(smem_dst), "l"(gsrc) : "memory");
}

// ---------------------------------------------------------------------------
// K0: zero the grid-barrier counters (stream-ordered before k_steps)
// ---------------------------------------------------------------------------
__global__ void k_zero_bar() {
    if (threadIdx.x < 2 * S_) g_bar[threadIdx.x] = 0;
}

// ---------------------------------------------------------------------------
// K1: embedding gather.  grid = S*B blocks, 64 threads (float4 row copy)
// ---------------------------------------------------------------------------
__global__ void k_gather(const int* __restrict__ concepts,
                         const float* __restrict__ table) {
    int tb  = blockIdx.x;                      // t*B + b
    int tok = concepts[tb];
    const float4* src = reinterpret_cast<const float4*>(table + (size_t)tok * E_);
    float4*       dst = reinterpret_cast<float4*>(g_emb + (size_t)tb * E_);
    dst[threadIdx.x] = src[threadIdx.x];
}

// ---------------------------------------------------------------------------
// K1b: tiled transpose  src[M][N] -> dst[N][M]   (M,N multiples of 32)
// ---------------------------------------------------------------------------
__global__ void k_transpose(const float* __restrict__ src, float* __restrict__ dst,
                            int M, int N) {
    __shared__ float t[32][33];
    int nb = blockIdx.x * 32, mb = blockIdx.y * 32;
    int tx = threadIdx.x, ty = threadIdx.y;   // (32, 8)
#pragma unroll
    for (int i = 0; i < 4; i++)
        t[ty + i * 8][tx] = src[(size_t)(mb + ty + i * 8) * N + nb + tx];
    __syncthreads();
#pragma unroll
    for (int i = 0; i < 4; i++)
        dst[(size_t)(nb + ty + i * 8) * M + mb + tx] = t[tx][ty + i * 8];
}

// ---------------------------------------------------------------------------
// K1c: Wih transpose WITH duplication:  dst[e][2n] = dst[e][2n+1] = src[n][e]
//      src = Wih [1024][256]; dst row = 2048 floats.  blockIdx.z = dir.
// ---------------------------------------------------------------------------
__global__ void k_wtransdup(const float* __restrict__ w0, const float* __restrict__ w1) {
    __shared__ float t[32][33];
    const float* src = blockIdx.z ? w1 : w0;
    float* dst = g_WihT2 + (size_t)blockIdx.z * E_ * 2 * G4_;
    int eb = blockIdx.x * 32, nb = blockIdx.y * 32;
    int tx = threadIdx.x, ty = threadIdx.y;   // (32, 8)
#pragma unroll
    for (int i = 0; i < 4; i++)
        t[ty + i * 8][tx] = src[(size_t)(nb + ty + i * 8) * E_ + eb + tx];   // t[n_l][e_l]
    __syncthreads();
#pragma unroll
    for (int i = 0; i < 4; i++) {
        float v = t[tx][ty + i * 8];          // (e_l = ty+i*8, n_l = tx)
        float2 d = make_float2(v, v);
        *reinterpret_cast<float2*>(dst + (size_t)(eb + ty + i * 8) * (2 * G4_)
                                       + 2 * (nb + tx)) = d;
    }
}

// ---------------------------------------------------------------------------
// K2: x-projection GEMM  X[dir] = emb @ Wih[dir]^T + b[dir]
//     M=8192, N=1024, K=256.  BM=128, BN=64, BK=16, 256 thr, 4x4 microtile
//     with f32x2 lanes = adjacent m pairs.  B pre-duplicated {b,b} in global
//     (g_WihT2) so the inner loop has ZERO pack instructions:
//     per k: 2 LDS.128 (A pairs) + 2 LDS.128 (B dup) + 16 FFMA2 = 20 issue.
// ---------------------------------------------------------------------------
__global__ __launch_bounds__(256) void k_xgemm(const float* __restrict__ b_f,
                                               const float* __restrict__ b_b) {
    const int dir = blockIdx.z;
    const float* __restrict__ AT   = g_embT;                                // [k][8192]
    const float* __restrict__ BT   = g_WihT2 + (size_t)dir * E_ * 2 * G4_;  // [k][2048] dup
    const float* __restrict__ bias = dir ? b_b : b_f;
    float* __restrict__ Xout = g_X + (size_t)dir * S_ * B_ * G4_;

    __shared__ float As[2][16][132];   // [stage][k][m]      8448 B/stage
    __shared__ float Bs[2][16][132];   // [stage][k][2n dup] 8448 B/stage (128 used)

    const int m0  = blockIdx.x * 128;
    const int n0  = blockIdx.y * 64;
    const int tid = threadIdx.x;
    const int tx  = tid & 15;       // -> n quad (4 n = 8 dup floats)
    const int ty  = tid >> 4;       // -> m oct (8 m = 4 pairs)

    const uint32_t as_sa = (uint32_t)__cvta_generic_to_shared(&As[0][0][0]);
    const uint32_t bs_sa = (uint32_t)__cvta_generic_to_shared(&Bs[0][0][0]);
    // A: 512 quads/stage -> 2 per thread
    const int rA = tid >> 5;            // k row 0..7
    const int cA = (tid & 31) * 4;      // m col 0..124
    // B(dup): 16 k x 128 floats = 512 quads/stage -> 2 per thread
    const int rB = tid >> 5;            // k row 0..7
    const int cB = (tid & 31) * 4;      // dup col 0..124

    auto load_stage = [&](int st, int kc) {
        uint32_t abase = as_sa + st * (16 * 132 * 4);
        uint32_t bbase = bs_sa + st * (16 * 132 * 4);
        cp16(abase + (rA * 132 + cA) * 4,       AT + (size_t)(kc + rA) * 8192 + m0 + cA);
        cp16(abase + ((rA + 8) * 132 + cA) * 4, AT + (size_t)(kc + rA + 8) * 8192 + m0 + cA);
        cp16(bbase + (rB * 132 + cB) * 4,       BT + (size_t)(kc + rB) * 2048 + 2 * n0 + cB);
        cp16(bbase + ((rB + 8) * 132 + cB) * 4, BT + (size_t)(kc + rB + 8) * 2048 + 2 * n0 + cB);
        asm volatile("cp.async.commit_group;" ::: "memory");
    };

    ull acc2[4][4];   // [m-pair][n]
#pragma unroll
    for (int i = 0; i < 4; i++)
#pragma unroll
        for (int j = 0; j < 4; j++) acc2[i][j] = 0ull;

    load_stage(0, 0);
#pragma unroll 1
    for (int it = 0; it < 16; ++it) {
        const int cur = it & 1;
        if (it < 15) load_stage(cur ^ 1, (it + 1) * 16);
        if (it < 15) asm volatile("cp.async.wait_group 1;" ::: "memory");
        else         asm volatile("cp.async.wait_group 0;" ::: "memory");
        __syncthreads();
#pragma unroll
        for (int k = 0; k < 16; k++) {
            ulonglong2 aa0 = *reinterpret_cast<const ulonglong2*>(&As[cur][k][ty * 8]);
            ulonglong2 aa1 = *reinterpret_cast<const ulonglong2*>(&As[cur][k][ty * 8 + 4]);
            ulonglong2 bb0 = *reinterpret_cast<const ulonglong2*>(&Bs[cur][k][tx * 8]);
            ulonglong2 bb1 = *reinterpret_cast<const ulonglong2*>(&Bs[cur][k][tx * 8 + 4]);
            ull am[4] = { aa0.x, aa0.y, aa1.x, aa1.y };       // {m0,m1}..{m6,m7}
            ull bd[4] = { bb0.x, bb0.y, bb1.x, bb1.y };       // {n0,n0}..{n3,n3}
#pragma unroll
            for (int i = 0; i < 4; i++) {
                ffma2(acc2[i][0], am[i], bd[0]);
                ffma2(acc2[i][1], am[i], bd[1]);
                ffma2(acc2[i][2], am[i], bd[2]);
                ffma2(acc2[i][3], am[i], bd[3]);
            }
        }
        __syncthreads();
    }

    // epilogue: lanes = (m even, m odd); assemble per-row float4 + bias
    float bv0 = bias[n0 + tx * 4 + 0];
    float bv1 = bias[n0 + tx * 4 + 1];
    float bv2 = bias[n0 + tx * 4 + 2];
    float bv3 = bias[n0 + tx * 4 + 3];
#pragma unroll
    for (int i = 0; i < 4; i++) {
        float2 e0 = unpack2(acc2[i][0]);
        float2 e1 = unpack2(acc2[i][1]);
        float2 e2 = unpack2(acc2[i][2]);
        float2 e3 = unpack2(acc2[i][3]);
        int m_even = m0 + ty * 8 + i * 2;
        float4 oe, oo;
        oe.x = e0.x + bv0; oe.y = e1.x + bv1; oe.z = e2.x + bv2; oe.w = e3.x + bv3;
        oo.x = e0.y + bv0; oo.y = e1.y + bv1; oo.z = e2.y + bv2; oo.w = e3.y + bv3;
        *reinterpret_cast<float4*>(Xout + (size_t)m_even * G4_ + n0 + tx * 4)       = oe;
        *reinterpret_cast<float4*>(Xout + (size_t)(m_even + 1) * G4_ + n0 + tx * 4) = oo;
    }
}

// ---------------------------------------------------------------------------
// K3: persistent BiLSTM recurrence — R10 verbatim (proven 516us form).
// ---------------------------------------------------------------------------
__global__ __launch_bounds__(512, 1) void k_steps(const int* __restrict__ lens,
                                                  const float* __restrict__ Whh_f,
                                                  const float* __restrict__ Whh_b) {
    __shared__ float w_s[256][16];        // [k][row]  16 KB (transposed Whh slice)
    __shared__ float part_s[8][16][64];   // k-slice partial gates  32 KB

    const int tid = threadIdx.x;
    const int dir = blockIdx.x >> 6;
    const int cb  = blockIdx.x & 63;
    const int j0  = cb * 4;
    const float* __restrict__ Whh = dir ? Whh_b : Whh_f;
    const float* __restrict__ X   = g_X + (size_t)dir * S_ * B_ * G4_;

    {
        int row = tid >> 5;                 // 0..15 (= gate*4 + ch)
        int gg  = row >> 2, ch = row & 3;
        int grw = gg * H_ + j0 + ch;
        const float* src = Whh + (size_t)grw * H_ + (tid & 31) * 8;
#pragma unroll
        for (int u = 0; u < 8; u += 4) {
            float4 v = *reinterpret_cast<const float4*>(src + u);
            int k0 = (tid & 31) * 8 + u;
            w_s[k0 + 0][row] = v.x;
            w_s[k0 + 1][row] = v.y;
            w_s[k0 + 2][row] = v.z;
            w_s[k0 + 3][row] = v.w;
        }
    }

    const int ks = tid >> 6;               // k-slice 0..7 (32 k each)
    const int rq = (tid >> 3) & 3;         // row quad 0..3
    const int bq = (((tid >> 5) & 1) << 3) | (tid & 7);   // batch quad 0..15
    const int r0 = rq * 4;
    const int b0 = bq * 4;
    const int kbase = ks * 32;

    const bool pw  = (tid < 256);
    const int  pch = tid >> 6;         // 0..3 channel within CTA (valid when pw)
    const int  pb  = tid & 63;         // batch
    const int  Lp  = pw ? __ldg(lens + pb) : 0;
    float creg = 0.0f;

    float* __restrict__ houtB = g_h + (size_t)dir * S_ * B_ * H_;
    int* barp = g_bar + dir * S_;

    float xg0 = 0.f, xg1 = 0.f, xg2 = 0.f, xg3 = 0.f;
    if (pw) {
        int m;
        if (dir == 0) m = pb;
        else { int rr = (0 < Lp) ? (Lp - 1) : 0; m = rr * B_ + pb; }
        const float* Xm = X + (size_t)m * G4_ + j0 + pch;
        xg0 = Xm[0 * H_]; xg1 = Xm[1 * H_]; xg2 = Xm[2 * H_]; xg3 = Xm[3 * H_];
    }
    __syncthreads();   // w_s ready

    for (int t = 0; t < S_; ++t) {
        if (t > 0) {
            ull a00 = 0, a01 = 0, a10 = 0, a11 = 0, a20 = 0, a21 = 0, a30 = 0, a31 = 0;
            const float* hsrc = &g_hT[dir][(t - 1) & 1][0][0] + (size_t)kbase * 64 + b0;
#pragma unroll 8
            for (int kk = 0; kk < 32; ++kk) {
                ull hx, hy;
                ldcg128(hx, hy, hsrc + kk * 64);
                float4 wv = *reinterpret_cast<const float4*>(&w_s[kbase + kk][r0]);
                ull w0 = pack2(wv.x, wv.x), w1 = pack2(wv.y, wv.y);
                ull w2 = pack2(wv.z, wv.z), w3 = pack2(wv.w, wv.w);
                ffma2(a00, w0, hx); ffma2(a01, w0, hy);
                ffma2(a10, w1, hx); ffma2(a11, w1, hy);
                ffma2(a20, w2, hx); ffma2(a21, w2, hy);
                ffma2(a30, w3, hx); ffma2(a31, w3, hy);
            }
            float2 l0 = unpack2(a00), h0 = unpack2(a01);
            float2 l1 = unpack2(a10), h1 = unpack2(a11);
            float2 l2 = unpack2(a20), h2v = unpack2(a21);
            float2 l3 = unpack2(a30), h3 = unpack2(a31);
            *reinterpret_cast<float4*>(&part_s[ks][r0 + 0][b0]) = make_float4(l0.x, l0.y, h0.x, h0.y);
            *reinterpret_cast<float4*>(&part_s[ks][r0 + 1][b0]) = make_float4(l1.x, l1.y, h1.x, h1.y);
            *reinterpret_cast<float4*>(&part_s[ks][r0 + 2][b0]) = make_float4(l2.x, l2.y, h2v.x, h2v.y);
            *reinterpret_cast<float4*>(&part_s[ks][r0 + 3][b0]) = make_float4(l3.x, l3.y, h3.x, h3.y);
            __syncthreads();
        }

        if (pw) {
            float gv0 = xg0, gv1 = xg1, gv2 = xg2, gv3 = xg3;
            if (t > 0) {
#pragma unroll
                for (int s = 0; s < 8; ++s) {
                    gv0 += part_s[s][0 * 4 + pch][pb];
                    gv1 += part_s[s][1 * 4 + pch][pb];
                    gv2 += part_s[s][2 * 4 + pch][pb];
                    gv3 += part_s[s][3 * 4 + pch][pb];
                }
            }
            float cn = fsig(gv1) * creg + fsig(gv0) * ftanh(gv2);
            float hn = fsig(gv3) * ftanh(cn);
            creg = cn;
            houtB[(size_t)t * B_ * H_ + pb * H_ + j0 + pch] = hn;
            stcg32(&g_hT[dir][t & 1][j0 + pch][pb], hn);
        }

        if (t < S_ - 1) {
            __syncthreads();                 // h(t) stores done CTA-wide
            if (tid == 0)
                asm volatile("red.release.gpu.global.add.s32 [%0], 1;" :: "l"(barp + t) : "memory");

            if (pw) {
                int tn = t + 1;
                int m;
                if (dir == 0) m = tn * B_ + pb;
                else { int rr = (tn < Lp) ? (Lp - 1 - tn) : tn; m = rr * B_ + pb; }
                const float* Xm = X + (size_t)m * G4_ + j0 + pch;
                xg0 = Xm[0 * H_]; xg1 = Xm[1 * H_]; xg2 = Xm[2 * H_]; xg3 = Xm[3 * H_];
            }

            if (tid == 0) {
                int guard = 1 << 20;
                int v;
                do {
                    asm volatile("ld.acquire.gpu.global.s32 %0, [%1];" : "=r"(v) : "l"(barp + t) : "memory");
                } while (v < NCTA_DIR && --guard);
            }
            __syncthreads();
        }
    }
}

// ---------------------------------------------------------------------------
// K4: u/w projections.  Block = (b, s-group of 8), 512 threads.
// ---------------------------------------------------------------------------
__global__ __launch_bounds__(512) void k_uw(const int* __restrict__ lens,
                                            const float* __restrict__ Ua,
                                            const float* __restrict__ Wa) {
    __shared__ float enc_s[8][516];

    const int b  = blockIdx.x;
    const int sg = blockIdx.y;
    const int tid = threadIdx.x;
    const int L = lens[b];

    {
        int lr = tid >> 6;             // local s row 0..7
        int lc = (tid & 63) * 8;       // col 0..504 step 8
        int s_row = sg * 8 + lr;
        bool valid = (s_row < L);
        int ridx = valid ? (L - 1 - s_row) : s_row;
        const float* src = (lc < 256)
            ? g_h + (size_t)s_row * B_ * H_ + b * H_ + lc
            : g_h + (size_t)S_ * B_ * H_ + (size_t)ridx * B_ * H_ + b * H_ + (lc - 256);
        float4 v0 = make_float4(0.f, 0.f, 0.f, 0.f);
        float4 v1 = v0;
        if (valid) {
            v0 = *reinterpret_cast<const float4*>(src);
            v1 = *reinterpret_cast<const float4*>(src + 4);
        }
        *reinterpret_cast<float4*>(&enc_s[lr][lc])     = v0;
        *reinterpret_cast<float4*>(&enc_s[lr][lc + 4]) = v1;
    }
    __syncthreads();

    const int row = tid >> 3;
    const int sl  = tid & 7;
    if (row < 2 * HID_) {
        const float* __restrict__ Wrow =
            (row < HID_) ? (Ua + (size_t)row * 2 * H_) : (Wa + (size_t)(row - HID_) * 2 * H_);
        float acc = 0.f;
#pragma unroll 8
        for (int k = 0; k < 2 * H_; k += 4) {
            float4 wv = *reinterpret_cast<const float4*>(Wrow + k);
            float4 ev = *reinterpret_cast<const float4*>(&enc_s[sl][k]);
            acc += wv.x * ev.x + wv.y * ev.y + wv.z * ev.z + wv.w * ev.w;
        }
        int s = sg * 8 + sl;
        if (row < HID_)
            g_U[((size_t)b * S_ + s) * HID_ + row] = acc;
        else
            g_Wt[(size_t)b * HID_ * S_ + (size_t)(row - HID_) * S_ + s] = acc;
    }
}

// ---------------------------------------------------------------------------
// K5: scores + predictions (MUFU tanh).
// ---------------------------------------------------------------------------
__global__ void k_scores(const float* __restrict__ va, float* __restrict__ out) {
    const int i = blockIdx.x;
    const int b = blockIdx.y;
    const int j = threadIdx.x;   // 128

    __shared__ float u_s[HID_];
    __shared__ float va_s[HID_];
    if (j < HID_) {
        u_s[j]  = g_U[((size_t)b * S_ + i) * HID_ + j];
        va_s[j] = va[j];
    }
    __syncthreads();

    const float* __restrict__ Wb = g_Wt + (size_t)b * HID_ * S_;
    float acc = 0.f;
#pragma unroll
    for (int k = 0; k < HID_; k++) {
        float wv = Wb[k * S_ + j];
        acc += ftanh(u_s[k] + wv) * va_s[k];
    }
    size_t idx = ((size_t)b * S_ + i) * S_ + j;
    out[idx] = acc;
    out[(size_t)B_ * S_ * S_ + idx] = (acc >= 0.0f) ? 1.0f : 0.0f;
}

// ---------------------------------------------------------------------------
extern "C" void kernel_launch(void* const* d_in, const int* in_sizes, int n_in,
                              void* d_out, int out_size) {
    const int*   concepts = (const int*)d_in[0];
    const int*   lens     = (const int*)d_in[1];
    const float* emb      = (const float*)d_in[2];
    const float* Wih_f    = (const float*)d_in[3];
    const float* Whh_f    = (const float*)d_in[4];
    const float* b_f      = (const float*)d_in[5];
    const float* Wih_b    = (const float*)d_in[6];
    const float* Whh_b    = (const float*)d_in[7];
    const float* b_b      = (const float*)d_in[8];
    const float* Ua       = (const float*)d_in[9];
    const float* Wa       = (const float*)d_in[10];
    const float* va       = (const float*)d_in[11];
    float* out = (float*)d_out;

    float* embT_p = nullptr;
    float* emb_p  = nullptr;
    cudaGetSymbolAddress((void**)&embT_p, g_embT);
    cudaGetSymbolAddress((void**)&emb_p,  g_emb);

    k_zero_bar<<<1, 256>>>();
    k_gather<<<S_ * B_, 64>>>(concepts, emb);
    k_transpose<<<dim3(E_ / 32, (S_ * B_) / 32), dim3(32, 8)>>>(emb_p, embT_p, S_ * B_, E_);
    k_wtransdup<<<dim3(E_ / 32, G4_ / 32, 2), dim3(32, 8)>>>(Wih_f, Wih_b);
    k_xgemm<<<dim3(64, 16, 2), 256>>>(b_f, b_b);
    k_steps<<<2 * NCTA_DIR, 512>>>(lens, Whh_f, Whh_b);
    k_uw<<<dim3(B_, S_ / 8), 512>>>(lens, Ua, Wa);
    k_scores<<<dim3(S_, B_), 128>>>(va, out);
}

// round 17
// speedup vs baseline: 1.1823x; 1.1823x over previous
#include <cuda_runtime.h>
#include <math.h>
#include <stdint.h>

typedef unsigned long long ull;

// Problem constants
constexpr int S_   = 128;   // sequence length
constexpr int B_   = 64;    // batch
constexpr int E_   = 256;   // embedding dim
constexpr int H_   = 256;   // hidden
constexpr int G4_  = 1024;  // 4*H (gates)
constexpr int HID_ = 30;    // attention hidden
constexpr int NCTA_DIR = 64;   // CTAs per direction in persistent step kernel

// Scratch (static device globals — no runtime allocation)
__device__ float g_emb[S_ * B_ * E_];        // (t,b,e)
__device__ float g_embT[E_ * S_ * B_];       // transposed: [e][t*B+b]
__device__ float g_WihT[2 * E_ * G4_];       // transposed Wih per dir: [k][n]
__device__ float g_X[2 * S_ * B_ * G4_];     // x-projections per dir, bias folded in
__device__ float g_h[2 * S_ * B_ * H_];      // [dir][t][b][k]  (for K4)
__device__ float g_hT[2][2][H_][B_];         // ping-pong [dir][parity][k][b]
__device__ int   g_bar[2 * S_];              // grid-barrier arrival counters
__device__ float g_U[B_ * S_ * HID_];        // u = enc @ Ua^T
__device__ float g_Wt[B_ * HID_ * S_];       // w transposed: [b][k][s]

// fast activations: MUFU-based, rel err ~2e-7 (budget is 1e-3)
__device__ __forceinline__ float fsig(float x)  { return 1.0f / (1.0f + __expf(-x)); }
__device__ __forceinline__ float ftanh(float x) { return 2.0f / (1.0f + __expf(-2.0f * x)) - 1.0f; }

// pure (non-volatile) packed fp32 math — scheduler may move these freely
__device__ __forceinline__ void ffma2(ull& d, ull a, ull b) {
    asm("fma.rn.f32x2 %0, %1, %2, %0;" : "+l"(d) : "l"(a), "l"(b));
}
__device__ __forceinline__ ull pack2(float lo, float hi) {
    ull r; asm("mov.b64 %0, {%1, %2};" : "=l"(r) : "f"(lo), "f"(hi)); return r;
}
__device__ __forceinline__ float2 unpack2(ull v) {
    float2 r; asm("mov.b64 {%0, %1}, %2;" : "=f"(r.x), "=f"(r.y) : "l"(v)); return r;
}
// L1-bypassing 16B load (h produced by other CTAs within this launch)
__device__ __forceinline__ void ldcg128(ull& x, ull& y, const float* p) {
    asm volatile("ld.global.cg.v2.u64 {%0, %1}, [%2];" : "=l"(x), "=l"(y) : "l"(p));
}
__device__ __forceinline__ void stcg32(float* p, float v) {
    asm volatile("st.global.cg.f32 [%0], %1;" :: "l"(p), "f"(v));
}
__device__ __forceinline__ void cp16(uint32_t smem_dst, const void* gsrc) {
    asm volatile("cp.async.cg.shared.global [%0], [%1], 16;" :: "r"(smem_dst), "l"(gsrc) : "memory");
}

// ---------------------------------------------------------------------------
// K0: zero the grid-barrier counters (stream-ordered before k_steps)
// ---------------------------------------------------------------------------
__global__ void k_zero_bar() {
    if (threadIdx.x < 2 * S_) g_bar[threadIdx.x] = 0;
}

// ---------------------------------------------------------------------------
// K1: embedding gather.  grid = S*B blocks, 64 threads (float4 row copy)
// ---------------------------------------------------------------------------
__global__ void k_gather(const int* __restrict__ concepts,
                         const float* __restrict__ table) {
    int tb  = blockIdx.x;                      // t*B + b
    int tok = concepts[tb];
    const float4* src = reinterpret_cast<const float4*>(table + (size_t)tok * E_);
    float4*       dst = reinterpret_cast<float4*>(g_emb + (size_t)tb * E_);
    dst[threadIdx.x] = src[threadIdx.x];
}

// ---------------------------------------------------------------------------
// K1b: tiled transpose  src[M][N] -> dst[N][M]   (M,N multiples of 32)
// ---------------------------------------------------------------------------
__global__ void k_transpose(const float* __restrict__ src, float* __restrict__ dst,
                            int M, int N) {
    __shared__ float t[32][33];
    int nb = blockIdx.x * 32, mb = blockIdx.y * 32;
    int tx = threadIdx.x, ty = threadIdx.y;   // (32, 8)
#pragma unroll
    for (int i = 0; i < 4; i++)
        t[ty + i * 8][tx] = src[(size_t)(mb + ty + i * 8) * N + nb + tx];
    __syncthreads();
#pragma unroll
    for (int i = 0; i < 4; i++)
        dst[(size_t)(nb + ty + i * 8) * M + mb + tx] = t[tx][ty + i * 8];
}

// ---------------------------------------------------------------------------
// K2: x-projection GEMM  X[dir] = emb @ Wih[dir]^T + b[dir]
//     M=8192, N=1024, K=256.  BM=128, BN=64, BK=16, 256 thr.
//     Memory layout / staging identical to the proven 792.8us config
//     (As[2][16][132], Bs[2][16][68], same cp.async double buffer).
//     Compute mapping changed: accumulators = 4 m-pairs x 4 n, A read as
//     ulonglong2 pairs (broadcast), B as one float4 + 4 packs.
//     Inner loop per k: 3 LDS + 4 packs + 16 FFMA2 = 23 issue (was 27).
// ---------------------------------------------------------------------------
__global__ __launch_bounds__(256) void k_xgemm(const float* __restrict__ b_f,
                                               const float* __restrict__ b_b) {
    const int dir = blockIdx.z;
    const float* __restrict__ AT   = g_embT;                      // [k][8192]
    const float* __restrict__ BT   = g_WihT + (size_t)dir * E_ * G4_;  // [k][1024]
    const float* __restrict__ bias = dir ? b_b : b_f;
    float* __restrict__ Xout = g_X + (size_t)dir * S_ * B_ * G4_;

    __shared__ float As[2][16][132];   // [stage][k][m]  8448 B/stage
    __shared__ float Bs[2][16][68];    // [stage][k][n]  4352 B/stage

    const int m0  = blockIdx.x * 128;
    const int n0  = blockIdx.y * 64;
    const int tid = threadIdx.x;
    const int tx  = tid & 15;       // -> n quad (4 wide)
    const int ty  = tid >> 4;       // -> m oct (8 wide = 4 pairs)

    const uint32_t as_sa = (uint32_t)__cvta_generic_to_shared(&As[0][0][0]);
    const uint32_t bs_sa = (uint32_t)__cvta_generic_to_shared(&Bs[0][0][0]);
    // A: 512 quads/stage -> 2 per thread (q=tid, tid+256: same col, k+8)
    const int rA = tid >> 5;            // k row 0..7
    const int cA = (tid & 31) * 4;      // m col 0..124
    // B: 256 quads/stage -> 1 per thread
    const int rB = tid >> 4;            // k row 0..15
    const int cB = (tid & 15) * 4;      // n col 0..60

    auto load_stage = [&](int st, int kc) {
        uint32_t abase = as_sa + st * (16 * 132 * 4);
        uint32_t bbase = bs_sa + st * (16 * 68 * 4);
        cp16(abase + (rA * 132 + cA) * 4,       AT + (size_t)(kc + rA) * 8192 + m0 + cA);
        cp16(abase + ((rA + 8) * 132 + cA) * 4, AT + (size_t)(kc + rA + 8) * 8192 + m0 + cA);
        cp16(bbase + (rB * 68 + cB) * 4,        BT + (size_t)(kc + rB) * 1024 + n0 + cB);
        asm volatile("cp.async.commit_group;" ::: "memory");
    };

    ull acc2[4][4];   // [m-pair][n]
#pragma unroll
    for (int i = 0; i < 4; i++)
#pragma unroll
        for (int j = 0; j < 4; j++) acc2[i][j] = 0ull;

    load_stage(0, 0);
#pragma unroll 1
    for (int it = 0; it < 16; ++it) {
        const int cur = it & 1;
        if (it < 15) load_stage(cur ^ 1, (it + 1) * 16);
        if (it < 15) asm volatile("cp.async.wait_group 1;" ::: "memory");
        else         asm volatile("cp.async.wait_group 0;" ::: "memory");
        __syncthreads();
#pragma unroll
        for (int k = 0; k < 16; k++) {
            ulonglong2 aa0 = *reinterpret_cast<const ulonglong2*>(&As[cur][k][ty * 8]);
            ulonglong2 aa1 = *reinterpret_cast<const ulonglong2*>(&As[cur][k][ty * 8 + 4]);
            float4 bb = *reinterpret_cast<const float4*>(&Bs[cur][k][tx * 4]);
            ull am[4] = { aa0.x, aa0.y, aa1.x, aa1.y };       // {m0,m1}..{m6,m7}
            ull bd0 = pack2(bb.x, bb.x);
            ull bd1 = pack2(bb.y, bb.y);
            ull bd2 = pack2(bb.z, bb.z);
            ull bd3 = pack2(bb.w, bb.w);
#pragma unroll
            for (int i = 0; i < 4; i++) {
                ffma2(acc2[i][0], am[i], bd0);
                ffma2(acc2[i][1], am[i], bd1);
                ffma2(acc2[i][2], am[i], bd2);
                ffma2(acc2[i][3], am[i], bd3);
            }
        }
        __syncthreads();
    }

    // epilogue: lanes = (m even, m odd); assemble per-row float4 + bias
    float bv0 = bias[n0 + tx * 4 + 0];
    float bv1 = bias[n0 + tx * 4 + 1];
    float bv2 = bias[n0 + tx * 4 + 2];
    float bv3 = bias[n0 + tx * 4 + 3];
#pragma unroll
    for (int i = 0; i < 4; i++) {
        float2 e0 = unpack2(acc2[i][0]);
        float2 e1 = unpack2(acc2[i][1]);
        float2 e2 = unpack2(acc2[i][2]);
        float2 e3 = unpack2(acc2[i][3]);
        int m_even = m0 + ty * 8 + i * 2;
        float4 oe, oo;
        oe.x = e0.x + bv0; oe.y = e1.x + bv1; oe.z = e2.x + bv2; oe.w = e3.x + bv3;
        oo.x = e0.y + bv0; oo.y = e1.y + bv1; oo.z = e2.y + bv2; oo.w = e3.y + bv3;
        *reinterpret_cast<float4*>(Xout + (size_t)m_even * G4_ + n0 + tx * 4)       = oe;
        *reinterpret_cast<float4*>(Xout + (size_t)(m_even + 1) * G4_ + n0 + tx * 4) = oo;
    }
}

// ---------------------------------------------------------------------------
// K3: persistent BiLSTM recurrence — R10 verbatim (proven 516us form).
// ---------------------------------------------------------------------------
__global__ __launch_bounds__(512, 1) void k_steps(const int* __restrict__ lens,
                                                  const float* __restrict__ Whh_f,
                                                  const float* __restrict__ Whh_b) {
    __shared__ float w_s[256][16];        // [k][row]  16 KB (transposed Whh slice)
    __shared__ float part_s[8][16][64];   // k-slice partial gates  32 KB

    const int tid = threadIdx.x;
    const int dir = blockIdx.x >> 6;
    const int cb  = blockIdx.x & 63;
    const int j0  = cb * 4;
    const float* __restrict__ Whh = dir ? Whh_b : Whh_f;
    const float* __restrict__ X   = g_X + (size_t)dir * S_ * B_ * G4_;

    {
        int row = tid >> 5;                 // 0..15 (= gate*4 + ch)
        int gg  = row >> 2, ch = row & 3;
        int grw = gg * H_ + j0 + ch;
        const float* src = Whh + (size_t)grw * H_ + (tid & 31) * 8;
#pragma unroll
        for (int u = 0; u < 8; u += 4) {
            float4 v = *reinterpret_cast<const float4*>(src + u);
            int k0 = (tid & 31) * 8 + u;
            w_s[k0 + 0][row] = v.x;
            w_s[k0 + 1][row] = v.y;
            w_s[k0 + 2][row] = v.z;
            w_s[k0 + 3][row] = v.w;
        }
    }

    const int ks = tid >> 6;               // k-slice 0..7 (32 k each)
    const int rq = (tid >> 3) & 3;         // row quad 0..3
    const int bq = (((tid >> 5) & 1) << 3) | (tid & 7);   // batch quad 0..15
    const int r0 = rq * 4;
    const int b0 = bq * 4;
    const int kbase = ks * 32;

    const bool pw  = (tid < 256);
    const int  pch = tid >> 6;         // 0..3 channel within CTA (valid when pw)
    const int  pb  = tid & 63;         // batch
    const int  Lp  = pw ? __ldg(lens + pb) : 0;
    float creg = 0.0f;

    float* __restrict__ houtB = g_h + (size_t)dir * S_ * B_ * H_;
    int* barp = g_bar + dir * S_;

    float xg0 = 0.f, xg1 = 0.f, xg2 = 0.f, xg3 = 0.f;
    if (pw) {
        int m;
        if (dir == 0) m = pb;
        else { int rr = (0 < Lp) ? (Lp - 1) : 0; m = rr * B_ + pb; }
        const float* Xm = X + (size_t)m * G4_ + j0 + pch;
        xg0 = Xm[0 * H_]; xg1 = Xm[1 * H_]; xg2 = Xm[2 * H_]; xg3 = Xm[3 * H_];
    }
    __syncthreads();   // w_s ready

    for (int t = 0; t < S_; ++t) {
        if (t > 0) {
            ull a00 = 0, a01 = 0, a10 = 0, a11 = 0, a20 = 0, a21 = 0, a30 = 0, a31 = 0;
            const float* hsrc = &g_hT[dir][(t - 1) & 1][0][0] + (size_t)kbase * 64 + b0;
#pragma unroll 8
            for (int kk = 0; kk < 32; ++kk) {
                ull hx, hy;
                ldcg128(hx, hy, hsrc + kk * 64);
                float4 wv = *reinterpret_cast<const float4*>(&w_s[kbase + kk][r0]);
                ull w0 = pack2(wv.x, wv.x), w1 = pack2(wv.y, wv.y);
                ull w2 = pack2(wv.z, wv.z), w3 = pack2(wv.w, wv.w);
                ffma2(a00, w0, hx); ffma2(a01, w0, hy);
                ffma2(a10, w1, hx); ffma2(a11, w1, hy);
                ffma2(a20, w2, hx); ffma2(a21, w2, hy);
                ffma2(a30, w3, hx); ffma2(a31, w3, hy);
            }
            float2 l0 = unpack2(a00), h0 = unpack2(a01);
            float2 l1 = unpack2(a10), h1 = unpack2(a11);
            float2 l2 = unpack2(a20), h2v = unpack2(a21);
            float2 l3 = unpack2(a30), h3 = unpack2(a31);
            *reinterpret_cast<float4*>(&part_s[ks][r0 + 0][b0]) = make_float4(l0.x, l0.y, h0.x, h0.y);
            *reinterpret_cast<float4*>(&part_s[ks][r0 + 1][b0]) = make_float4(l1.x, l1.y, h1.x, h1.y);
            *reinterpret_cast<float4*>(&part_s[ks][r0 + 2][b0]) = make_float4(l2.x, l2.y, h2v.x, h2v.y);
            *reinterpret_cast<float4*>(&part_s[ks][r0 + 3][b0]) = make_float4(l3.x, l3.y, h3.x, h3.y);
            __syncthreads();
        }

        if (pw) {
            float gv0 = xg0, gv1 = xg1, gv2 = xg2, gv3 = xg3;
            if (t > 0) {
#pragma unroll
                for (int s = 0; s < 8; ++s) {
                    gv0 += part_s[s][0 * 4 + pch][pb];
                    gv1 += part_s[s][1 * 4 + pch][pb];
                    gv2 += part_s[s][2 * 4 + pch][pb];
                    gv3 += part_s[s][3 * 4 + pch][pb];
                }
            }
            float cn = fsig(gv1) * creg + fsig(gv0) * ftanh(gv2);
            float hn = fsig(gv3) * ftanh(cn);
            creg = cn;
            houtB[(size_t)t * B_ * H_ + pb * H_ + j0 + pch] = hn;
            stcg32(&g_hT[dir][t & 1][j0 + pch][pb], hn);
        }

        if (t < S_ - 1) {
            __syncthreads();                 // h(t) stores done CTA-wide
            if (tid == 0)
                asm volatile("red.release.gpu.global.add.s32 [%0], 1;" :: "l"(barp + t) : "memory");

            if (pw) {
                int tn = t + 1;
                int m;
                if (dir == 0) m = tn * B_ + pb;
                else { int rr = (tn < Lp) ? (Lp - 1 - tn) : tn; m = rr * B_ + pb; }
                const float* Xm = X + (size_t)m * G4_ + j0 + pch;
                xg0 = Xm[0 * H_]; xg1 = Xm[1 * H_]; xg2 = Xm[2 * H_]; xg3 = Xm[3 * H_];
            }

            if (tid == 0) {
                int guard = 1 << 20;
                int v;
                do {
                    asm volatile("ld.acquire.gpu.global.s32 %0, [%1];" : "=r"(v) : "l"(barp + t) : "memory");
                } while (v < NCTA_DIR && --guard);
            }
            __syncthreads();
        }
    }
}

// ---------------------------------------------------------------------------
// K4: u/w projections.  Block = (b, s-group of 8), 512 threads.
// ---------------------------------------------------------------------------
__global__ __launch_bounds__(512) void k_uw(const int* __restrict__ lens,
                                            const float* __restrict__ Ua,
                                            const float* __restrict__ Wa) {
    __shared__ float enc_s[8][516];

    const int b  = blockIdx.x;
    const int sg = blockIdx.y;
    const int tid = threadIdx.x;
    const int L = lens[b];

    {
        int lr = tid >> 6;             // local s row 0..7
        int lc = (tid & 63) * 8;       // col 0..504 step 8
        int s_row = sg * 8 + lr;
        bool valid = (s_row < L);
        int ridx = valid ? (L - 1 - s_row) : s_row;
        const float* src = (lc < 256)
            ? g_h + (size_t)s_row * B_ * H_ + b * H_ + lc
            : g_h + (size_t)S_ * B_ * H_ + (size_t)ridx * B_ * H_ + b * H_ + (lc - 256);
        float4 v0 = make_float4(0.f, 0.f, 0.f, 0.f);
        float4 v1 = v0;
        if (valid) {
            v0 = *reinterpret_cast<const float4*>(src);
            v1 = *reinterpret_cast<const float4*>(src + 4);
        }
        *reinterpret_cast<float4*>(&enc_s[lr][lc])     = v0;
        *reinterpret_cast<float4*>(&enc_s[lr][lc + 4]) = v1;
    }
    __syncthreads();

    const int row = tid >> 3;
    const int sl  = tid & 7;
    if (row < 2 * HID_) {
        const float* __restrict__ Wrow =
            (row < HID_) ? (Ua + (size_t)row * 2 * H_) : (Wa + (size_t)(row - HID_) * 2 * H_);
        float acc = 0.f;
#pragma unroll 8
        for (int k = 0; k < 2 * H_; k += 4) {
            float4 wv = *reinterpret_cast<const float4*>(Wrow + k);
            float4 ev = *reinterpret_cast<const float4*>(&enc_s[sl][k]);
            acc += wv.x * ev.x + wv.y * ev.y + wv.z * ev.z + wv.w * ev.w;
        }
        int s = sg * 8 + sl;
        if (row < HID_)
            g_U[((size_t)b * S_ + s) * HID_ + row] = acc;
        else
            g_Wt[(size_t)b * HID_ * S_ + (size_t)(row - HID_) * S_ + s] = acc;
    }
}

// ---------------------------------------------------------------------------
// K5: scores + predictions (MUFU tanh).
// ---------------------------------------------------------------------------
__global__ void k_scores(const float* __restrict__ va, float* __restrict__ out) {
    const int i = blockIdx.x;
    const int b = blockIdx.y;
    const int j = threadIdx.x;   // 128

    __shared__ float u_s[HID_];
    __shared__ float va_s[HID_];
    if (j < HID_) {
        u_s[j]  = g_U[((size_t)b * S_ + i) * HID_ + j];
        va_s[j] = va[j];
    }
    __syncthreads();

    const float* __restrict__ Wb = g_Wt + (size_t)b * HID_ * S_;
    float acc = 0.f;
#pragma unroll
    for (int k = 0; k < HID_; k++) {
        float wv = Wb[k * S_ + j];
        acc += ftanh(u_s[k] + wv) * va_s[k];
    }
    size_t idx = ((size_t)b * S_ + i) * S_ + j;
    out[idx] = acc;
    out[(size_t)B_ * S_ * S_ + idx] = (acc >= 0.0f) ? 1.0f : 0.0f;
}

// ---------------------------------------------------------------------------
extern "C" void kernel_launch(void* const* d_in, const int* in_sizes, int n_in,
                              void* d_out, int out_size) {
    const int*   concepts = (const int*)d_in[0];
    const int*   lens     = (const int*)d_in[1];
    const float* emb      = (const float*)d_in[2];
    const float* Wih_f    = (const float*)d_in[3];
    const float* Whh_f    = (const float*)d_in[4];
    const float* b_f      = (const float*)d_in[5];
    const float* Wih_b    = (const float*)d_in[6];
    const float* Whh_b    = (const float*)d_in[7];
    const float* b_b      = (const float*)d_in[8];
    const float* Ua       = (const float*)d_in[9];
    const float* Wa       = (const float*)d_in[10];
    const float* va       = (const float*)d_in[11];
    float* out = (float*)d_out;

    float* embT_p = nullptr;
    float* WihT_p = nullptr;
    float* emb_p  = nullptr;
    cudaGetSymbolAddress((void**)&embT_p, g_embT);
    cudaGetSymbolAddress((void**)&WihT_p, g_WihT);
    cudaGetSymbolAddress((void**)&emb_p,  g_emb);

    k_zero_bar<<<1, 256>>>();
    k_gather<<<S_ * B_, 64>>>(concepts, emb);
    k_transpose<<<dim3(E_ / 32, (S_ * B_) / 32), dim3(32, 8)>>>(emb_p, embT_p, S_ * B_, E_);
    k_transpose<<<dim3(E_ / 32, G4_ / 32), dim3(32, 8)>>>(Wih_f, WihT_p, G4_, E_);
    k_transpose<<<dim3(E_ / 32, G4_ / 32), dim3(32, 8)>>>(Wih_b, WihT_p + E_ * G4_, G4_, E_);
    k_xgemm<<<dim3(64, 16, 2), 256>>>(b_f, b_b);
    k_steps<<<2 * NCTA_DIR, 512>>>(lens, Whh_f, Whh_b);
    k_uw<<<dim3(B_, S_ / 8), 512>>>(lens, Ua, Wa);
    k_scores<<<dim3(S_, B_), 128>>>(va, out);
}